// round 1
// baseline (speedup 1.0000x reference)
#include <cuda_runtime.h>
#include <math.h>

#define BATCH 8
#define SEQ   2048
#define HID   1024

// Scratch (device globals — no allocation allowed)
__device__ float g_Q[(size_t)BATCH * SEQ * HID];
__device__ float g_K[(size_t)BATCH * SEQ * HID];
__device__ float g_V[(size_t)BATCH * SEQ * HID];
__device__ float g_S[(size_t)BATCH * SEQ * SEQ];

// ---------------------------------------------------------------------------
// Classic 128x128x16 SGEMM, 256 threads, 8x8 per-thread microtile.
// A: [M,K] row-major. B: [K,N] row-major (TRANSB=false) or [N,K] row-major
// (TRANSB=true, i.e. C = A * B^T). Batched via blockIdx.z with given strides.
// All problem dims here are multiples of 128 (M,N) and 16 (K): no bounds checks.
// ---------------------------------------------------------------------------
template<bool TRANSB, bool ADD_BIAS>
__global__ __launch_bounds__(256) void sgemm_kernel(
    const float* __restrict__ A, const float* __restrict__ B,
    const float* __restrict__ bias, float* __restrict__ C,
    int M, int N, int K, long sA, long sB, long sC)
{
    constexpr int BK = 16;
    __shared__ float As[BK][128];
    __shared__ float Bs[BK][128];

    const int tid = threadIdx.x;
    const int bn = blockIdx.x, bm = blockIdx.y, bz = blockIdx.z;
    A += (long)bz * sA;
    B += (long)bz * sB;
    C += (long)bz * sC;

    const int tx = tid & 15;   // column group (8 cols each)
    const int ty = tid >> 4;   // row group (8 rows each)

    float acc[8][8];
    #pragma unroll
    for (int i = 0; i < 8; i++)
        #pragma unroll
        for (int j = 0; j < 8; j++) acc[i][j] = 0.f;

    for (int k0 = 0; k0 < K; k0 += BK) {
        // ---- load A tile (128 x 16), transpose into As[k][m] ----
        #pragma unroll
        for (int s = tid; s < 512; s += 256) {
            int row = s >> 2;            // 0..127
            int col = (s & 3) << 2;      // 0,4,8,12
            float4 v = *(const float4*)(A + (long)(bm * 128 + row) * K + k0 + col);
            As[col + 0][row] = v.x;
            As[col + 1][row] = v.y;
            As[col + 2][row] = v.z;
            As[col + 3][row] = v.w;
        }
        // ---- load B tile into Bs[k][n] ----
        if constexpr (!TRANSB) {
            #pragma unroll
            for (int s = tid; s < 512; s += 256) {
                int row = s >> 5;            // 0..15 (k)
                int col = (s & 31) << 2;     // 0..124 (n)
                float4 v = *(const float4*)(B + (long)(k0 + row) * N + bn * 128 + col);
                *(float4*)&Bs[row][col] = v;
            }
        } else {
            #pragma unroll
            for (int s = tid; s < 512; s += 256) {
                int n  = s >> 2;             // 0..127
                int kk = (s & 3) << 2;       // 0,4,8,12
                float4 v = *(const float4*)(B + (long)(bn * 128 + n) * K + k0 + kk);
                Bs[kk + 0][n] = v.x;
                Bs[kk + 1][n] = v.y;
                Bs[kk + 2][n] = v.z;
                Bs[kk + 3][n] = v.w;
            }
        }
        __syncthreads();

        // ---- compute ----
        #pragma unroll
        for (int kk = 0; kk < BK; kk++) {
            float ra[8], rb[8];
            *(float4*)&ra[0] = *(const float4*)&As[kk][ty * 8 + 0];
            *(float4*)&ra[4] = *(const float4*)&As[kk][ty * 8 + 4];
            *(float4*)&rb[0] = *(const float4*)&Bs[kk][tx * 8 + 0];
            *(float4*)&rb[4] = *(const float4*)&Bs[kk][tx * 8 + 4];
            #pragma unroll
            for (int i = 0; i < 8; i++)
                #pragma unroll
                for (int j = 0; j < 8; j++)
                    acc[i][j] = fmaf(ra[i], rb[j], acc[i][j]);
        }
        __syncthreads();
    }

    // ---- epilogue ----
    #pragma unroll
    for (int i = 0; i < 8; i++) {
        long row = (long)bm * 128 + ty * 8 + i;
        #pragma unroll
        for (int j = 0; j < 8; j += 4) {
            int col = bn * 128 + tx * 8 + j;
            float4 v = make_float4(acc[i][j], acc[i][j + 1], acc[i][j + 2], acc[i][j + 3]);
            if constexpr (ADD_BIAS) {
                v.x += bias[col + 0];
                v.y += bias[col + 1];
                v.z += bias[col + 2];
                v.w += bias[col + 3];
            }
            *(float4*)(C + row * N + col) = v;
        }
    }
}

// ---------------------------------------------------------------------------
// Fused scale + mask + softmax over rows of the [B,S,S] score matrix, in place.
// scores' = softmax over k of (scores[q][k] * inv_scale, masked -> -inf)
// ---------------------------------------------------------------------------
__global__ __launch_bounds__(256) void softmax_kernel(
    float* __restrict__ S, const int* __restrict__ mask, float inv_scale)
{
    const int row = blockIdx.x;
    const int b   = blockIdx.y;
    float* ptr = S + ((long)b * SEQ + row) * SEQ;
    const int* mrow = mask + (long)b * SEQ;
    const int tid = threadIdx.x;

    __shared__ float red[256];

    float m = -INFINITY;
    for (int k = tid; k < SEQ; k += 256) {
        float v = (mrow[k] == 0) ? -INFINITY : ptr[k] * inv_scale;
        m = fmaxf(m, v);
    }
    red[tid] = m; __syncthreads();
    for (int o = 128; o > 0; o >>= 1) {
        if (tid < o) red[tid] = fmaxf(red[tid], red[tid + o]);
        __syncthreads();
    }
    m = red[0];
    __syncthreads();

    float sum = 0.f;
    for (int k = tid; k < SEQ; k += 256) {
        float v = (mrow[k] == 0) ? -INFINITY : ptr[k] * inv_scale;
        float e = __expf(v - m);
        ptr[k] = e;
        sum += e;
    }
    red[tid] = sum; __syncthreads();
    for (int o = 128; o > 0; o >>= 1) {
        if (tid < o) red[tid] += red[tid + o];
        __syncthreads();
    }
    float inv = 1.f / red[0];
    __syncthreads();

    for (int k = tid; k < SEQ; k += 256) ptr[k] *= inv;
}

// ---------------------------------------------------------------------------
extern "C" void kernel_launch(void* const* d_in, const int* in_sizes, int n_in,
                              void* d_out, int out_size)
{
    const float* inp  = (const float*)d_in[0];
    const int*   mask = (const int*)  d_in[1];
    const float* Wq   = (const float*)d_in[2];
    const float* bq   = (const float*)d_in[3];
    const float* Wk   = (const float*)d_in[4];
    const float* bk   = (const float*)d_in[5];
    const float* Wv   = (const float*)d_in[6];
    const float* bv   = (const float*)d_in[7];
    float* out = (float*)d_out;

    float *Q, *K, *V, *Sc;
    cudaGetSymbolAddress((void**)&Q,  g_Q);
    cudaGetSymbolAddress((void**)&K,  g_K);
    cudaGetSymbolAddress((void**)&V,  g_V);
    cudaGetSymbolAddress((void**)&Sc, g_S);

    dim3 blk(256);

    // QKV projections: [16384,1024] x [1024,1024] + bias
    dim3 g1(HID / 128, (BATCH * SEQ) / 128, 1);
    sgemm_kernel<false, true><<<g1, blk>>>(inp, Wq, bq, Q, BATCH * SEQ, HID, HID, 0, 0, 0);
    sgemm_kernel<false, true><<<g1, blk>>>(inp, Wk, bk, K, BATCH * SEQ, HID, HID, 0, 0, 0);
    sgemm_kernel<false, true><<<g1, blk>>>(inp, Wv, bv, V, BATCH * SEQ, HID, HID, 0, 0, 0);

    // scores = Q @ K^T (batched NT), [2048,2048] per batch
    dim3 g2(SEQ / 128, SEQ / 128, BATCH);
    sgemm_kernel<true, false><<<g2, blk>>>(Q, K, nullptr, Sc, SEQ, SEQ, HID,
                                           (long)SEQ * HID, (long)SEQ * HID, (long)SEQ * SEQ);

    // softmax(scores / sqrt(H)) with mask, in place
    dim3 g3(SEQ, BATCH);
    softmax_kernel<<<g3, blk>>>(Sc, mask, 1.0f / 32.0f);  // 1/sqrt(1024)

    // out = attn @ V (batched NN), [2048,1024] per batch
    dim3 g4(HID / 128, SEQ / 128, BATCH);
    sgemm_kernel<false, false><<<g4, blk>>>(Sc, V, nullptr, out, SEQ, HID, SEQ,
                                            (long)SEQ * SEQ, (long)SEQ * HID, (long)SEQ * HID);
}

// round 3
// speedup vs baseline: 2.6135x; 2.6135x over previous
#include <cuda_runtime.h>
#include <cuda_bf16.h>
#include <math.h>
#include <stdint.h>

#define BATCH 8
#define SEQ   2048
#define HID   1024
#define BS    (BATCH*SEQ)

typedef __nv_bfloat16 bf16;

// ---------------------------------------------------------------------------
// Scratch (device globals — allocation is forbidden)
// ---------------------------------------------------------------------------
__device__ bf16 g_Xhi[(size_t)BS * HID],  g_Xlo[(size_t)BS * HID];
__device__ bf16 g_Wqt_hi[(size_t)HID * HID], g_Wqt_lo[(size_t)HID * HID];
__device__ bf16 g_Wkt_hi[(size_t)HID * HID], g_Wkt_lo[(size_t)HID * HID];
__device__ bf16 g_Wvt_hi[(size_t)HID * HID], g_Wvt_lo[(size_t)HID * HID];
__device__ bf16 g_Qhi[(size_t)BS * HID],  g_Qlo[(size_t)BS * HID];
__device__ bf16 g_Khi[(size_t)BS * HID],  g_Klo[(size_t)BS * HID];
__device__ bf16 g_Vhi[(size_t)BS * HID],  g_Vlo[(size_t)BS * HID];
__device__ bf16 g_Vthi[(size_t)BS * HID], g_Vtlo[(size_t)BS * HID];
__device__ float g_S[(size_t)BATCH * SEQ * SEQ];
__device__ bf16 g_Phi[(size_t)BATCH * SEQ * SEQ], g_Plo[(size_t)BATCH * SEQ * SEQ];

// ---------------------------------------------------------------------------
// Helpers
// ---------------------------------------------------------------------------
__device__ __forceinline__ uint32_t smem_u32(const void* p) {
    uint32_t a;
    asm("{ .reg .u64 t; cvta.to.shared.u64 t, %1; cvt.u32.u64 %0, t; }" : "=r"(a) : "l"(p));
    return a;
}

__device__ __forceinline__ void cp_async16(uint32_t dst, const void* src) {
    asm volatile("cp.async.cg.shared.global [%0], [%1], 16;" :: "r"(dst), "l"(src));
}
__device__ __forceinline__ void cp_commit() {
    asm volatile("cp.async.commit_group;");
}
template<int N>
__device__ __forceinline__ void cp_wait() {
    asm volatile("cp.async.wait_group %0;" :: "n"(N));
}

__device__ __forceinline__ void ldsm4(uint32_t* r, uint32_t addr) {
    asm volatile("ldmatrix.sync.aligned.m8n8.x4.shared.b16 {%0,%1,%2,%3}, [%4];"
                 : "=r"(r[0]), "=r"(r[1]), "=r"(r[2]), "=r"(r[3]) : "r"(addr));
}

__device__ __forceinline__ void mma16816(float* d, const uint32_t* a, const uint32_t* b) {
    asm volatile(
        "mma.sync.aligned.m16n8k16.row.col.f32.bf16.bf16.f32 "
        "{%0,%1,%2,%3}, {%4,%5,%6,%7}, {%8,%9}, {%0,%1,%2,%3};"
        : "+f"(d[0]), "+f"(d[1]), "+f"(d[2]), "+f"(d[3])
        : "r"(a[0]), "r"(a[1]), "r"(a[2]), "r"(a[3]), "r"(b[0]), "r"(b[1]));
}

// SW128 swizzle of a byte offset within a tile of 128-byte rows
__device__ __forceinline__ uint32_t sw128(uint32_t off) {
    return off ^ ((off >> 3) & 0x70);
}

// ---------------------------------------------------------------------------
// Elementwise split: fp32 -> (hi, lo) bf16
// ---------------------------------------------------------------------------
__global__ __launch_bounds__(256) void split_kernel(
    const float* __restrict__ x, bf16* __restrict__ hi, bf16* __restrict__ lo, long n)
{
    long i = ((long)blockIdx.x * 256 + threadIdx.x) * 4;
    if (i >= n) return;
    float4 v = *(const float4*)(x + i);
    float f[4] = {v.x, v.y, v.z, v.w};
    bf16 h[4], l[4];
    #pragma unroll
    for (int j = 0; j < 4; j++) {
        h[j] = __float2bfloat16(f[j]);
        l[j] = __float2bfloat16(f[j] - __bfloat162float(h[j]));
    }
    __nv_bfloat162 h01, h23, l01, l23;
    h01.x = h[0]; h01.y = h[1]; h23.x = h[2]; h23.y = h[3];
    l01.x = l[0]; l01.y = l[1]; l23.x = l[2]; l23.y = l[3];
    *(__nv_bfloat162*)(hi + i)     = h01;
    *(__nv_bfloat162*)(hi + i + 2) = h23;
    *(__nv_bfloat162*)(lo + i)     = l01;
    *(__nv_bfloat162*)(lo + i + 2) = l23;
}

// W [K=H, N=H] fp32 -> Wt [N, K] (hi, lo) bf16   (Wt[n][k] = W[k][n])
__global__ __launch_bounds__(256) void wtrans_kernel(
    const float* __restrict__ W, bf16* __restrict__ hi, bf16* __restrict__ lo)
{
    __shared__ float t[32][33];
    int tx = threadIdx.x, ty = threadIdx.y;
    int x0 = blockIdx.x * 32, y0 = blockIdx.y * 32;
    #pragma unroll
    for (int r = 0; r < 32; r += 8)
        t[ty + r][tx] = W[(long)(y0 + ty + r) * HID + x0 + tx];
    __syncthreads();
    #pragma unroll
    for (int r = 0; r < 32; r += 8) {
        float v = t[tx][ty + r];
        long o = (long)(x0 + ty + r) * HID + y0 + tx;
        bf16 h = __float2bfloat16(v);
        hi[o] = h;
        lo[o] = __float2bfloat16(v - __bfloat162float(h));
    }
}

// bf16 batched transpose: in [R, C] -> out [C, R] per batch (blockIdx.z)
__global__ __launch_bounds__(256) void btrans_kernel(
    const bf16* __restrict__ in, bf16* __restrict__ out, int R, int C)
{
    __shared__ bf16 t[32][33];
    int tx = threadIdx.x, ty = threadIdx.y;
    int x0 = blockIdx.x * 32, y0 = blockIdx.y * 32;
    in  += (long)blockIdx.z * R * C;
    out += (long)blockIdx.z * R * C;
    #pragma unroll
    for (int r = 0; r < 32; r += 8)
        t[ty + r][tx] = in[(long)(y0 + ty + r) * C + x0 + tx];
    __syncthreads();
    #pragma unroll
    for (int r = 0; r < 32; r += 8)
        out[(long)(x0 + ty + r) * R + y0 + tx] = t[tx][ty + r];
}

// ---------------------------------------------------------------------------
// HMMA bf16-split GEMM: C[m][n] = sum_k (Ahi+Alo)[m][k] * (Bhi+Blo)[n][k]
// A: [M,K] K-major bf16 (hi/lo).  B: [N,K] K-major bf16 (hi/lo).
// CTA tile 128x128, BK=64, 256 threads (8 warps, 4Mx2N, warp tile 32x64).
// Double-buffered SMEM via cp.async. SW128 swizzle, ldmatrix fragments,
// 3 accumulating mma.sync per operand pair (hi*hi + hi*lo + lo*hi).
// ---------------------------------------------------------------------------
#define TILE_BYTES  16384                 // 128 rows x 128 bytes (64 bf16)
#define BUF_BYTES   (4 * TILE_BYTES)      // Ahi, Alo, Bhi, Blo
#define GEMM_SMEM   (2 * BUF_BYTES + 1024)

// Load one 128x64 bf16 tile (global, row stride ldk elems) into swizzled SMEM.
__device__ __forceinline__ void load_tile_async(
    uint32_t dst, const bf16* __restrict__ src, int ldk, int tid)
{
    #pragma unroll
    for (int i = 0; i < 4; i++) {
        int s = tid + i * 256;
        int row = s >> 3, seg = s & 7;
        uint32_t off = row * 128 + seg * 16;
        cp_async16(dst + sw128(off), src + (long)row * ldk + seg * 8);
    }
}

template<bool ADD_BIAS, bool OUT_HILO>
__global__ __launch_bounds__(256, 1) void gemm_split_kernel(
    const bf16* __restrict__ Ahi, const bf16* __restrict__ Alo,
    const bf16* __restrict__ Bhi, const bf16* __restrict__ Blo,
    const float* __restrict__ bias,
    float* __restrict__ Cf, bf16* __restrict__ Chi, bf16* __restrict__ Clo,
    int K, int Ncols, long sA, long sB, long sC)
{
    extern __shared__ char smem[];
    const uint32_t tiles = (smem_u32(smem) + 1023) & ~1023u;

    const int tid = threadIdx.x;
    const int lane = tid & 31;
    const int w = tid >> 5;
    const int wm = w & 3;          // 0..3 : 32-row band
    const int wn = w >> 2;         // 0..1 : 64-col band
    const int bn = blockIdx.x, bm = blockIdx.y, bz = blockIdx.z;

    Ahi += bz * sA + (long)(bm * 128) * K;
    Alo += bz * sA + (long)(bm * 128) * K;
    Bhi += bz * sB + (long)(bn * 128) * K;
    Blo += bz * sB + (long)(bn * 128) * K;

    float acc[2][8][4];
    #pragma unroll
    for (int mt = 0; mt < 2; mt++)
        #pragma unroll
        for (int nt = 0; nt < 8; nt++)
            #pragma unroll
            for (int r = 0; r < 4; r++) acc[mt][nt][r] = 0.f;

    const int nchunks = K / 64;

    // prologue: chunk 0 into buffer 0
    {
        const uint32_t buf = tiles;
        load_tile_async(buf + 0 * TILE_BYTES, Ahi, K, tid);
        load_tile_async(buf + 1 * TILE_BYTES, Alo, K, tid);
        load_tile_async(buf + 2 * TILE_BYTES, Bhi, K, tid);
        load_tile_async(buf + 3 * TILE_BYTES, Blo, K, tid);
        cp_commit();
    }

    // ldmatrix base offsets (within a tile)
    const int arow = wm * 32 + (lane & 15);            // +mt*16
    const int brow = wn * 64 + (lane & 15);            // +nt2*16
    const uint32_t kseg = (lane >> 4) * 16;            // 16B half-select

    for (int c = 0; c < nchunks; c++) {
        const uint32_t buf = tiles + (c & 1) * BUF_BYTES;
        if (c + 1 < nchunks) {
            const uint32_t nbuf = tiles + ((c + 1) & 1) * BUF_BYTES;
            const long k0 = (long)(c + 1) * 64;
            load_tile_async(nbuf + 0 * TILE_BYTES, Ahi + k0, K, tid);
            load_tile_async(nbuf + 1 * TILE_BYTES, Alo + k0, K, tid);
            load_tile_async(nbuf + 2 * TILE_BYTES, Bhi + k0, K, tid);
            load_tile_async(nbuf + 3 * TILE_BYTES, Blo + k0, K, tid);
            cp_commit();
            cp_wait<1>();
        } else {
            cp_wait<0>();
        }
        __syncthreads();

        const uint32_t As_hi = buf + 0 * TILE_BYTES;
        const uint32_t As_lo = buf + 1 * TILE_BYTES;
        const uint32_t Bs_hi = buf + 2 * TILE_BYTES;
        const uint32_t Bs_lo = buf + 3 * TILE_BYTES;

        #pragma unroll
        for (int ks = 0; ks < 4; ks++) {
            const uint32_t kb = ks * 32 + kseg;   // byte col within 128B row
            uint32_t ah[2][4], al[2][4];
            #pragma unroll
            for (int mt = 0; mt < 2; mt++) {
                uint32_t off = (uint32_t)(arow + mt * 16) * 128 + kb;
                uint32_t sw = sw128(off);
                ldsm4(ah[mt], As_hi + sw);
                ldsm4(al[mt], As_lo + sw);
            }
            #pragma unroll
            for (int nt2 = 0; nt2 < 4; nt2++) {
                uint32_t off = (uint32_t)(brow + nt2 * 16) * 128 + kb;
                uint32_t sw = sw128(off);
                uint32_t rh[4], rl[4];
                ldsm4(rh, Bs_hi + sw);
                ldsm4(rl, Bs_lo + sw);
                uint32_t b0h[2] = {rh[0], rh[2]}, b1h[2] = {rh[1], rh[3]};
                uint32_t b0l[2] = {rl[0], rl[2]}, b1l[2] = {rl[1], rl[3]};
                #pragma unroll
                for (int mt = 0; mt < 2; mt++) {
                    mma16816(acc[mt][nt2 * 2 + 0], ah[mt], b0h);
                    mma16816(acc[mt][nt2 * 2 + 0], ah[mt], b0l);
                    mma16816(acc[mt][nt2 * 2 + 0], al[mt], b0h);
                    mma16816(acc[mt][nt2 * 2 + 1], ah[mt], b1h);
                    mma16816(acc[mt][nt2 * 2 + 1], ah[mt], b1l);
                    mma16816(acc[mt][nt2 * 2 + 1], al[mt], b1h);
                }
            }
        }
        __syncthreads();
    }

    // ---- epilogue ----
    const int qr = lane >> 2;      // 0..7
    const int qc = lane & 3;       // 0..3
    #pragma unroll
    for (int mt = 0; mt < 2; mt++) {
        #pragma unroll
        for (int half = 0; half < 2; half++) {   // d0,d1 vs d2,d3 (row, row+8)
            const long row = (long)(bm * 128 + wm * 32 + mt * 16 + qr + half * 8);
            const long cb = bz * sC + row * Ncols;
            #pragma unroll
            for (int nt = 0; nt < 8; nt++) {
                const int col = bn * 128 + wn * 64 + nt * 8 + qc * 2;
                float v0 = acc[mt][nt][half * 2 + 0];
                float v1 = acc[mt][nt][half * 2 + 1];
                if constexpr (ADD_BIAS) { v0 += bias[col]; v1 += bias[col + 1]; }
                if constexpr (OUT_HILO) {
                    __nv_bfloat162 h, l;
                    h.x = __float2bfloat16(v0);
                    h.y = __float2bfloat16(v1);
                    l.x = __float2bfloat16(v0 - __bfloat162float(h.x));
                    l.y = __float2bfloat16(v1 - __bfloat162float(h.y));
                    *(__nv_bfloat162*)(Chi + cb + col) = h;
                    *(__nv_bfloat162*)(Clo + cb + col) = l;
                } else {
                    float2 v = make_float2(v0, v1);
                    *(float2*)(Cf + cb + col) = v;
                }
            }
        }
    }
}

// ---------------------------------------------------------------------------
// Softmax over rows of scores [B,S,S]; emits probs as (hi, lo) bf16.
// ---------------------------------------------------------------------------
__global__ __launch_bounds__(256) void softmax_kernel(
    const float* __restrict__ S, const int* __restrict__ mask,
    bf16* __restrict__ Phi, bf16* __restrict__ Plo, float inv_scale)
{
    const int row = blockIdx.x;
    const int b   = blockIdx.y;
    const long off = ((long)b * SEQ + row) * SEQ;
    const float* ptr = S + off;
    const int* mrow = mask + (long)b * SEQ;
    const int tid = threadIdx.x;

    __shared__ float red[256];

    float m = -INFINITY;
    for (int k = tid; k < SEQ; k += 256) {
        float v = (mrow[k] == 0) ? -INFINITY : ptr[k] * inv_scale;
        m = fmaxf(m, v);
    }
    red[tid] = m; __syncthreads();
    for (int o = 128; o > 0; o >>= 1) {
        if (tid < o) red[tid] = fmaxf(red[tid], red[tid + o]);
        __syncthreads();
    }
    m = red[0];
    __syncthreads();

    float sum = 0.f;
    for (int k = tid; k < SEQ; k += 256) {
        float v = (mrow[k] == 0) ? -INFINITY : ptr[k] * inv_scale;
        sum += __expf(v - m);
    }
    red[tid] = sum; __syncthreads();
    for (int o = 128; o > 0; o >>= 1) {
        if (tid < o) red[tid] += red[tid + o];
        __syncthreads();
    }
    const float inv = 1.f / red[0];
    __syncthreads();

    for (int k = tid; k < SEQ; k += 256) {
        float v = (mrow[k] == 0) ? -INFINITY : ptr[k] * inv_scale;
        float p = __expf(v - m) * inv;
        bf16 h = __float2bfloat16(p);
        Phi[off + k] = h;
        Plo[off + k] = __float2bfloat16(p - __bfloat162float(h));
    }
}

// ---------------------------------------------------------------------------
extern "C" void kernel_launch(void* const* d_in, const int* in_sizes, int n_in,
                              void* d_out, int out_size)
{
    const float* inp  = (const float*)d_in[0];
    const int*   mask = (const int*)  d_in[1];
    const float* Wq   = (const float*)d_in[2];
    const float* bq   = (const float*)d_in[3];
    const float* Wk   = (const float*)d_in[4];
    const float* bk   = (const float*)d_in[5];
    const float* Wv   = (const float*)d_in[6];
    const float* bv   = (const float*)d_in[7];
    float* out = (float*)d_out;

    bf16 *Xhi, *Xlo, *Wqth, *Wqtl, *Wkth, *Wktl, *Wvth, *Wvtl;
    bf16 *Qhi, *Qlo, *Khi, *Klo, *Vhi, *Vlo, *Vthi, *Vtlo, *Phi, *Plo;
    float *Sc;
    cudaGetSymbolAddress((void**)&Xhi, g_Xhi);   cudaGetSymbolAddress((void**)&Xlo, g_Xlo);
    cudaGetSymbolAddress((void**)&Wqth, g_Wqt_hi); cudaGetSymbolAddress((void**)&Wqtl, g_Wqt_lo);
    cudaGetSymbolAddress((void**)&Wkth, g_Wkt_hi); cudaGetSymbolAddress((void**)&Wktl, g_Wkt_lo);
    cudaGetSymbolAddress((void**)&Wvth, g_Wvt_hi); cudaGetSymbolAddress((void**)&Wvtl, g_Wvt_lo);
    cudaGetSymbolAddress((void**)&Qhi, g_Qhi);   cudaGetSymbolAddress((void**)&Qlo, g_Qlo);
    cudaGetSymbolAddress((void**)&Khi, g_Khi);   cudaGetSymbolAddress((void**)&Klo, g_Klo);
    cudaGetSymbolAddress((void**)&Vhi, g_Vhi);   cudaGetSymbolAddress((void**)&Vlo, g_Vlo);
    cudaGetSymbolAddress((void**)&Vthi, g_Vthi); cudaGetSymbolAddress((void**)&Vtlo, g_Vtlo);
    cudaGetSymbolAddress((void**)&Phi, g_Phi);   cudaGetSymbolAddress((void**)&Plo, g_Plo);
    cudaGetSymbolAddress((void**)&Sc, g_S);

    cudaFuncSetAttribute(gemm_split_kernel<true, true>,
                         cudaFuncAttributeMaxDynamicSharedMemorySize, GEMM_SMEM);
    cudaFuncSetAttribute(gemm_split_kernel<false, false>,
                         cudaFuncAttributeMaxDynamicSharedMemorySize, GEMM_SMEM);

    // 1) split input to hi/lo bf16
    const long nX = (long)BS * HID;
    split_kernel<<<(unsigned)(nX / 1024), 256>>>(inp, Xhi, Xlo, nX);

    // 2) transpose+split weights:  Wt[n][k] = W[k][n]
    dim3 wgrid(HID / 32, HID / 32), wblk(32, 8);
    wtrans_kernel<<<wgrid, wblk>>>(Wq, Wqth, Wqtl);
    wtrans_kernel<<<wgrid, wblk>>>(Wk, Wkth, Wktl);
    wtrans_kernel<<<wgrid, wblk>>>(Wv, Wvth, Wvtl);

    // 3) QKV projections (tensor cores), epilogue writes hi/lo bf16
    dim3 gblk(256);
    dim3 g1(HID / 128, BS / 128, 1);
    gemm_split_kernel<true, true><<<g1, gblk, GEMM_SMEM>>>(
        Xhi, Xlo, Wqth, Wqtl, bq, nullptr, Qhi, Qlo, HID, HID, 0, 0, 0);
    gemm_split_kernel<true, true><<<g1, gblk, GEMM_SMEM>>>(
        Xhi, Xlo, Wkth, Wktl, bk, nullptr, Khi, Klo, HID, HID, 0, 0, 0);
    gemm_split_kernel<true, true><<<g1, gblk, GEMM_SMEM>>>(
        Xhi, Xlo, Wvth, Wvtl, bv, nullptr, Vhi, Vlo, HID, HID, 0, 0, 0);

    // 4) transpose V per batch: [S,H] -> [H,S]
    dim3 tgrid(HID / 32, SEQ / 32, BATCH), tblk(32, 8);
    btrans_kernel<<<tgrid, tblk>>>(Vhi, Vthi, SEQ, HID);
    btrans_kernel<<<tgrid, tblk>>>(Vlo, Vtlo, SEQ, HID);

    // 5) scores = Q @ K^T (batched), fp32 out
    dim3 g2(SEQ / 128, SEQ / 128, BATCH);
    gemm_split_kernel<false, false><<<g2, gblk, GEMM_SMEM>>>(
        Qhi, Qlo, Khi, Klo, nullptr, Sc, nullptr, nullptr,
        HID, SEQ, (long)SEQ * HID, (long)SEQ * HID, (long)SEQ * SEQ);

    // 6) masked scaled softmax -> probs hi/lo
    softmax_kernel<<<dim3(SEQ, BATCH), 256>>>(Sc, mask, Phi, Plo, 1.0f / 32.0f);

    // 7) out = P @ Vt^T (batched), fp32 out
    dim3 g3(HID / 128, SEQ / 128, BATCH);
    gemm_split_kernel<false, false><<<g3, gblk, GEMM_SMEM>>>(
        Phi, Plo, Vthi, Vtlo, nullptr, out, nullptr, nullptr,
        SEQ, HID, (long)SEQ * SEQ, (long)SEQ * HID, (long)SEQ * HID);
}

// round 4
// speedup vs baseline: 3.2699x; 1.2511x over previous
#include <cuda_runtime.h>
#include <cuda_fp16.h>
#include <math.h>
#include <stdint.h>

#define BATCH 8
#define SEQ   2048
#define HID   1024
#define BS    (BATCH*SEQ)

typedef __half fp16;

// ---------------------------------------------------------------------------
// Scratch (device globals — allocation is forbidden)
// ---------------------------------------------------------------------------
__device__ fp16 g_Xhi[(size_t)BS * HID],  g_Xlo[(size_t)BS * HID];
__device__ fp16 g_Wqt_hi[(size_t)HID * HID], g_Wqt_lo[(size_t)HID * HID];
__device__ fp16 g_Wkt_hi[(size_t)HID * HID], g_Wkt_lo[(size_t)HID * HID];
__device__ fp16 g_Wvt_hi[(size_t)HID * HID], g_Wvt_lo[(size_t)HID * HID];
__device__ fp16 g_Qhi[(size_t)BS * HID],  g_Qlo[(size_t)BS * HID];
__device__ fp16 g_Khi[(size_t)BS * HID],  g_Klo[(size_t)BS * HID];
__device__ fp16 g_Vh[(size_t)BS * HID];
__device__ fp16 g_Vt[(size_t)BS * HID];
__device__ float g_S[(size_t)BATCH * SEQ * SEQ];
__device__ fp16 g_P[(size_t)BATCH * SEQ * SEQ];

// ---------------------------------------------------------------------------
// Helpers
// ---------------------------------------------------------------------------
__device__ __forceinline__ uint32_t smem_u32(const void* p) {
    uint32_t a;
    asm("{ .reg .u64 t; cvta.to.shared.u64 t, %1; cvt.u32.u64 %0, t; }" : "=r"(a) : "l"(p));
    return a;
}

__device__ __forceinline__ void cp_async16(uint32_t dst, const void* src) {
    asm volatile("cp.async.cg.shared.global [%0], [%1], 16;" :: "r"(dst), "l"(src));
}
__device__ __forceinline__ void cp_commit() {
    asm volatile("cp.async.commit_group;");
}
template<int N>
__device__ __forceinline__ void cp_wait() {
    asm volatile("cp.async.wait_group %0;" :: "n"(N));
}

__device__ __forceinline__ void ldsm4(uint32_t* r, uint32_t addr) {
    asm volatile("ldmatrix.sync.aligned.m8n8.x4.shared.b16 {%0,%1,%2,%3}, [%4];"
                 : "=r"(r[0]), "=r"(r[1]), "=r"(r[2]), "=r"(r[3]) : "r"(addr));
}

__device__ __forceinline__ void mma16816(float* d, const uint32_t* a, const uint32_t* b) {
    asm volatile(
        "mma.sync.aligned.m16n8k16.row.col.f32.f16.f16.f32 "
        "{%0,%1,%2,%3}, {%4,%5,%6,%7}, {%8,%9}, {%0,%1,%2,%3};"
        : "+f"(d[0]), "+f"(d[1]), "+f"(d[2]), "+f"(d[3])
        : "r"(a[0]), "r"(a[1]), "r"(a[2]), "r"(a[3]), "r"(b[0]), "r"(b[1]));
}

// SW128 swizzle of a byte offset within a tile of 128-byte rows
__device__ __forceinline__ uint32_t sw128(uint32_t off) {
    return off ^ ((off >> 3) & 0x70);
}

// ---------------------------------------------------------------------------
// Elementwise split: fp32 -> (hi, lo) fp16
// ---------------------------------------------------------------------------
__global__ __launch_bounds__(256) void split_kernel(
    const float* __restrict__ x, fp16* __restrict__ hi, fp16* __restrict__ lo, long n)
{
    long i = ((long)blockIdx.x * 256 + threadIdx.x) * 4;
    if (i >= n) return;
    float4 v = *(const float4*)(x + i);
    float f[4] = {v.x, v.y, v.z, v.w};
    fp16 h[4], l[4];
    #pragma unroll
    for (int j = 0; j < 4; j++) {
        h[j] = __float2half_rn(f[j]);
        l[j] = __float2half_rn(f[j] - __half2float(h[j]));
    }
    *(half2*)(hi + i)     = __halves2half2(h[0], h[1]);
    *(half2*)(hi + i + 2) = __halves2half2(h[2], h[3]);
    *(half2*)(lo + i)     = __halves2half2(l[0], l[1]);
    *(half2*)(lo + i + 2) = __halves2half2(l[2], l[3]);
}

// W [K=H, N=H] fp32 -> Wt [N, K] (hi, lo) fp16, scaled by 32 (exact pow2).
// Scaling keeps lo-terms in fp16 normal range; epilogue multiplies by 1/32.
__global__ __launch_bounds__(256) void wtrans_kernel(
    const float* __restrict__ W, fp16* __restrict__ hi, fp16* __restrict__ lo)
{
    __shared__ float t[32][33];
    int tx = threadIdx.x, ty = threadIdx.y;
    int x0 = blockIdx.x * 32, y0 = blockIdx.y * 32;
    #pragma unroll
    for (int r = 0; r < 32; r += 8)
        t[ty + r][tx] = W[(long)(y0 + ty + r) * HID + x0 + tx];
    __syncthreads();
    #pragma unroll
    for (int r = 0; r < 32; r += 8) {
        float v = t[tx][ty + r] * 32.0f;
        long o = (long)(x0 + ty + r) * HID + y0 + tx;
        fp16 h = __float2half_rn(v);
        hi[o] = h;
        lo[o] = __float2half_rn(v - __half2float(h));
    }
}

// fp16 batched transpose: in [R, C] -> out [C, R] per batch (blockIdx.z)
__global__ __launch_bounds__(256) void btrans_kernel(
    const fp16* __restrict__ in, fp16* __restrict__ out, int R, int C)
{
    __shared__ fp16 t[32][33];
    int tx = threadIdx.x, ty = threadIdx.y;
    int x0 = blockIdx.x * 32, y0 = blockIdx.y * 32;
    in  += (long)blockIdx.z * R * C;
    out += (long)blockIdx.z * R * C;
    #pragma unroll
    for (int r = 0; r < 32; r += 8)
        t[ty + r][tx] = in[(long)(y0 + ty + r) * C + x0 + tx];
    __syncthreads();
    #pragma unroll
    for (int r = 0; r < 32; r += 8)
        out[(long)(x0 + ty + r) * R + y0 + tx] = t[tx][ty + r];
}

// ---------------------------------------------------------------------------
// HMMA fp16-split GEMM.
//   PRODUCTS==3: C = (Ahi+Alo)*(Bhi+Blo)^T  (drops lo*lo)
//   PRODUCTS==1: C = Ahi*Bhi^T
// A: [M,K] K-major.  B: [N,K] K-major.  CTA tile 128x128, BK=64,
// 256 threads (8 warps, 4Mx2N, warp tile 32x64), 3-stage cp.async pipeline.
// OUTMODE: 0 = fp32, 1 = fp16 hi/lo, 2 = fp16 single.
// Epilogue: v = acc*cscale (+ bias).
// ---------------------------------------------------------------------------
#define TILE_B   16384                 // 128 rows x 128 bytes (64 fp16)
#define STAGES   3

// Load one 128x64 fp16 tile (global, row stride ldk elems) into swizzled SMEM.
__device__ __forceinline__ void load_tile_async(
    uint32_t dst, const fp16* __restrict__ src, int ldk, int tid)
{
    #pragma unroll
    for (int i = 0; i < 4; i++) {
        int s = tid + i * 256;
        int row = s >> 3, seg = s & 7;
        uint32_t off = row * 128 + seg * 16;
        cp_async16(dst + sw128(off), src + (long)row * ldk + seg * 8);
    }
}

template<int OUTMODE, int PRODUCTS, bool ADD_BIAS>
__global__ __launch_bounds__(256, 1) void gemm_split_kernel(
    const fp16* __restrict__ Ahi, const fp16* __restrict__ Alo,
    const fp16* __restrict__ Bhi, const fp16* __restrict__ Blo,
    const float* __restrict__ bias, float cscale,
    float* __restrict__ Cf, fp16* __restrict__ Chi, fp16* __restrict__ Clo,
    int K, int Ncols, long sA, long sB, long sC)
{
    constexpr int NT = (PRODUCTS == 3) ? 4 : 2;
    constexpr uint32_t STAGE_B = NT * TILE_B;
    constexpr uint32_t OFF_AHI = 0;
    constexpr uint32_t OFF_ALO = 1 * TILE_B;                 // P3 only
    constexpr uint32_t OFF_BHI = (PRODUCTS == 3) ? 2 * TILE_B : 1 * TILE_B;
    constexpr uint32_t OFF_BLO = 3 * TILE_B;                 // P3 only

    extern __shared__ char smem[];
    const uint32_t tiles = (smem_u32(smem) + 1023) & ~1023u;

    const int tid = threadIdx.x;
    const int lane = tid & 31;
    const int w = tid >> 5;
    const int wm = w & 3;          // 0..3 : 32-row band
    const int wn = w >> 2;         // 0..1 : 64-col band
    const int bn = blockIdx.x, bm = blockIdx.y, bz = blockIdx.z;

    Ahi += bz * sA + (long)(bm * 128) * K;
    Bhi += bz * sB + (long)(bn * 128) * K;
    if (PRODUCTS == 3) {
        Alo += bz * sA + (long)(bm * 128) * K;
        Blo += bz * sB + (long)(bn * 128) * K;
    }

    float acc[2][8][4];
    #pragma unroll
    for (int mt = 0; mt < 2; mt++)
        #pragma unroll
        for (int nt = 0; nt < 8; nt++)
            #pragma unroll
            for (int r = 0; r < 4; r++) acc[mt][nt][r] = 0.f;

    const int nchunks = K / 64;

    auto issue_chunk = [&](int cc) {
        const uint32_t buf = tiles + (uint32_t)(cc % STAGES) * STAGE_B;
        const long k0 = (long)cc * 64;
        load_tile_async(buf + OFF_AHI, Ahi + k0, K, tid);
        if (PRODUCTS == 3) load_tile_async(buf + OFF_ALO, Alo + k0, K, tid);
        load_tile_async(buf + OFF_BHI, Bhi + k0, K, tid);
        if (PRODUCTS == 3) load_tile_async(buf + OFF_BLO, Blo + k0, K, tid);
        cp_commit();
    };

    // prologue: stages 0,1
    issue_chunk(0);
    issue_chunk(1);

    // ldmatrix base offsets (within a tile)
    const int arow = wm * 32 + (lane & 15);            // +mt*16
    const int brow = wn * 64 + (lane & 15);            // +nt2*16
    const uint32_t kseg = (lane >> 4) * 16;            // 16B half-select

    for (int c = 0; c < nchunks; c++) {
        if (c + 2 < nchunks) { issue_chunk(c + 2); cp_wait<2>(); }
        else if (c + 1 < nchunks) { cp_wait<1>(); }
        else { cp_wait<0>(); }
        __syncthreads();

        const uint32_t buf = tiles + (uint32_t)(c % STAGES) * STAGE_B;
        const uint32_t As_hi = buf + OFF_AHI;
        const uint32_t As_lo = buf + OFF_ALO;
        const uint32_t Bs_hi = buf + OFF_BHI;
        const uint32_t Bs_lo = buf + OFF_BLO;

        #pragma unroll
        for (int ks = 0; ks < 4; ks++) {
            const uint32_t kb = ks * 32 + kseg;   // byte col within 128B row
            uint32_t ah[2][4], al[2][4];
            #pragma unroll
            for (int mt = 0; mt < 2; mt++) {
                uint32_t off = (uint32_t)(arow + mt * 16) * 128 + kb;
                uint32_t sw = sw128(off);
                ldsm4(ah[mt], As_hi + sw);
                if (PRODUCTS == 3) ldsm4(al[mt], As_lo + sw);
            }
            #pragma unroll
            for (int nt2 = 0; nt2 < 4; nt2++) {
                uint32_t off = (uint32_t)(brow + nt2 * 16) * 128 + kb;
                uint32_t sw = sw128(off);
                uint32_t rh[4];
                ldsm4(rh, Bs_hi + sw);
                uint32_t b0h[2] = {rh[0], rh[2]}, b1h[2] = {rh[1], rh[3]};
                #pragma unroll
                for (int mt = 0; mt < 2; mt++) {
                    mma16816(acc[mt][nt2 * 2 + 0], ah[mt], b0h);
                    mma16816(acc[mt][nt2 * 2 + 1], ah[mt], b1h);
                }
                if (PRODUCTS == 3) {
                    uint32_t rl[4];
                    ldsm4(rl, Bs_lo + sw);
                    uint32_t b0l[2] = {rl[0], rl[2]}, b1l[2] = {rl[1], rl[3]};
                    #pragma unroll
                    for (int mt = 0; mt < 2; mt++) {
                        mma16816(acc[mt][nt2 * 2 + 0], ah[mt], b0l);
                        mma16816(acc[mt][nt2 * 2 + 1], ah[mt], b1l);
                        mma16816(acc[mt][nt2 * 2 + 0], al[mt], b0h);
                        mma16816(acc[mt][nt2 * 2 + 1], al[mt], b1h);
                    }
                }
            }
        }
        __syncthreads();
    }

    // ---- epilogue ----
    const int qr = lane >> 2;      // 0..7
    const int qc = lane & 3;       // 0..3
    #pragma unroll
    for (int mt = 0; mt < 2; mt++) {
        #pragma unroll
        for (int half_ = 0; half_ < 2; half_++) {   // d0,d1 vs d2,d3 (row, row+8)
            const long row = (long)(bm * 128 + wm * 32 + mt * 16 + qr + half_ * 8);
            const long cb = bz * sC + row * Ncols;
            #pragma unroll
            for (int nt = 0; nt < 8; nt++) {
                const int col = bn * 128 + wn * 64 + nt * 8 + qc * 2;
                float v0 = acc[mt][nt][half_ * 2 + 0] * cscale;
                float v1 = acc[mt][nt][half_ * 2 + 1] * cscale;
                if constexpr (ADD_BIAS) { v0 += bias[col]; v1 += bias[col + 1]; }
                if constexpr (OUTMODE == 0) {
                    *(float2*)(Cf + cb + col) = make_float2(v0, v1);
                } else if constexpr (OUTMODE == 1) {
                    fp16 h0 = __float2half_rn(v0);
                    fp16 h1 = __float2half_rn(v1);
                    fp16 l0 = __float2half_rn(v0 - __half2float(h0));
                    fp16 l1 = __float2half_rn(v1 - __half2float(h1));
                    *(half2*)(Chi + cb + col) = __halves2half2(h0, h1);
                    *(half2*)(Clo + cb + col) = __halves2half2(l0, l1);
                } else {
                    *(half2*)(Chi + cb + col) = __floats2half2_rn(v0, v1);
                }
            }
        }
    }
}

// ---------------------------------------------------------------------------
// Softmax over rows of scores [B,S,S] (already scaled by 1/32 in QK epilogue).
// Single global read (row cached in smem); emits probs as single fp16.
// ---------------------------------------------------------------------------
__global__ __launch_bounds__(256) void softmax_kernel(
    const float* __restrict__ S, const int* __restrict__ mask, fp16* __restrict__ P)
{
    const int row = blockIdx.x;
    const int b   = blockIdx.y;
    const long off = ((long)b * SEQ + row) * SEQ;
    const float* ptr = S + off;
    const int* mrow = mask + (long)b * SEQ;
    const int tid = threadIdx.x;

    __shared__ float buf[SEQ];
    __shared__ float red[256];

    float m = -INFINITY;
    #pragma unroll
    for (int k = tid * 4; k < SEQ; k += 1024) {
        float4 s = *(const float4*)(ptr + k);
        int4 mk = *(const int4*)(mrow + k);
        s.x = (mk.x == 0) ? -INFINITY : s.x;
        s.y = (mk.y == 0) ? -INFINITY : s.y;
        s.z = (mk.z == 0) ? -INFINITY : s.z;
        s.w = (mk.w == 0) ? -INFINITY : s.w;
        *(float4*)(buf + k) = s;
        m = fmaxf(m, fmaxf(fmaxf(s.x, s.y), fmaxf(s.z, s.w)));
    }
    red[tid] = m; __syncthreads();
    for (int o = 128; o > 0; o >>= 1) {
        if (tid < o) red[tid] = fmaxf(red[tid], red[tid + o]);
        __syncthreads();
    }
    m = red[0];
    __syncthreads();

    float sum = 0.f;
    #pragma unroll
    for (int k = tid * 4; k < SEQ; k += 1024) {
        float4 s = *(float4*)(buf + k);
        s.x = __expf(s.x - m); s.y = __expf(s.y - m);
        s.z = __expf(s.z - m); s.w = __expf(s.w - m);
        *(float4*)(buf + k) = s;
        sum += s.x + s.y + s.z + s.w;
    }
    red[tid] = sum; __syncthreads();
    for (int o = 128; o > 0; o >>= 1) {
        if (tid < o) red[tid] += red[tid + o];
        __syncthreads();
    }
    const float inv = 1.f / red[0];

    #pragma unroll
    for (int k = tid * 4; k < SEQ; k += 1024) {
        float4 e = *(float4*)(buf + k);
        *(half2*)(P + off + k)     = __floats2half2_rn(e.x * inv, e.y * inv);
        *(half2*)(P + off + k + 2) = __floats2half2_rn(e.z * inv, e.w * inv);
    }
}

// ---------------------------------------------------------------------------
extern "C" void kernel_launch(void* const* d_in, const int* in_sizes, int n_in,
                              void* d_out, int out_size)
{
    const float* inp  = (const float*)d_in[0];
    const int*   mask = (const int*)  d_in[1];
    const float* Wq   = (const float*)d_in[2];
    const float* bq   = (const float*)d_in[3];
    const float* Wk   = (const float*)d_in[4];
    const float* bk   = (const float*)d_in[5];
    const float* Wv   = (const float*)d_in[6];
    const float* bv   = (const float*)d_in[7];
    float* out = (float*)d_out;

    fp16 *Xhi, *Xlo, *Wqth, *Wqtl, *Wkth, *Wktl, *Wvth, *Wvtl;
    fp16 *Qhi, *Qlo, *Khi, *Klo, *Vh, *Vt, *P;
    float *Sc;
    cudaGetSymbolAddress((void**)&Xhi, g_Xhi);   cudaGetSymbolAddress((void**)&Xlo, g_Xlo);
    cudaGetSymbolAddress((void**)&Wqth, g_Wqt_hi); cudaGetSymbolAddress((void**)&Wqtl, g_Wqt_lo);
    cudaGetSymbolAddress((void**)&Wkth, g_Wkt_hi); cudaGetSymbolAddress((void**)&Wktl, g_Wkt_lo);
    cudaGetSymbolAddress((void**)&Wvth, g_Wvt_hi); cudaGetSymbolAddress((void**)&Wvtl, g_Wvt_lo);
    cudaGetSymbolAddress((void**)&Qhi, g_Qhi);   cudaGetSymbolAddress((void**)&Qlo, g_Qlo);
    cudaGetSymbolAddress((void**)&Khi, g_Khi);   cudaGetSymbolAddress((void**)&Klo, g_Klo);
    cudaGetSymbolAddress((void**)&Vh, g_Vh);     cudaGetSymbolAddress((void**)&Vt, g_Vt);
    cudaGetSymbolAddress((void**)&P, g_P);
    cudaGetSymbolAddress((void**)&Sc, g_S);

    const int SMEM_P3 = STAGES * 4 * TILE_B + 1024;   // 197632
    const int SMEM_P1 = STAGES * 2 * TILE_B + 1024;   // 99328
    cudaFuncSetAttribute(gemm_split_kernel<1, 3, true>,
                         cudaFuncAttributeMaxDynamicSharedMemorySize, SMEM_P3);
    cudaFuncSetAttribute(gemm_split_kernel<2, 3, true>,
                         cudaFuncAttributeMaxDynamicSharedMemorySize, SMEM_P3);
    cudaFuncSetAttribute(gemm_split_kernel<0, 3, false>,
                         cudaFuncAttributeMaxDynamicSharedMemorySize, SMEM_P3);
    cudaFuncSetAttribute(gemm_split_kernel<0, 1, false>,
                         cudaFuncAttributeMaxDynamicSharedMemorySize, SMEM_P1);

    const float inv32 = 1.0f / 32.0f;

    // 1) split input to hi/lo fp16
    const long nX = (long)BS * HID;
    split_kernel<<<(unsigned)(nX / 1024), 256>>>(inp, Xhi, Xlo, nX);

    // 2) transpose+split weights (x32):  Wt[n][k] = 32*W[k][n]
    dim3 wgrid(HID / 32, HID / 32), wblk(32, 8);
    wtrans_kernel<<<wgrid, wblk>>>(Wq, Wqth, Wqtl);
    wtrans_kernel<<<wgrid, wblk>>>(Wk, Wkth, Wktl);
    wtrans_kernel<<<wgrid, wblk>>>(Wv, Wvth, Wvtl);

    // 3) QKV projections: acc*(1/32) + bias.  Q,K -> hi/lo; V -> single fp16
    dim3 gblk(256);
    dim3 g1(HID / 128, BS / 128, 1);
    gemm_split_kernel<1, 3, true><<<g1, gblk, SMEM_P3>>>(
        Xhi, Xlo, Wqth, Wqtl, bq, inv32, nullptr, Qhi, Qlo, HID, HID, 0, 0, 0);
    gemm_split_kernel<1, 3, true><<<g1, gblk, SMEM_P3>>>(
        Xhi, Xlo, Wkth, Wktl, bk, inv32, nullptr, Khi, Klo, HID, HID, 0, 0, 0);
    gemm_split_kernel<2, 3, true><<<g1, gblk, SMEM_P3>>>(
        Xhi, Xlo, Wvth, Wvtl, bv, inv32, nullptr, Vh, nullptr, HID, HID, 0, 0, 0);

    // 4) transpose V per batch: [S,H] -> [H,S]
    dim3 tgrid(HID / 32, SEQ / 32, BATCH), tblk(32, 8);
    btrans_kernel<<<tgrid, tblk>>>(Vh, Vt, SEQ, HID);

    // 5) scores = (Q @ K^T)/32 (batched), fp32 out
    dim3 g2(SEQ / 128, SEQ / 128, BATCH);
    gemm_split_kernel<0, 3, false><<<g2, gblk, SMEM_P3>>>(
        Qhi, Qlo, Khi, Klo, nullptr, inv32, Sc, nullptr, nullptr,
        HID, SEQ, (long)SEQ * HID, (long)SEQ * HID, (long)SEQ * SEQ);

    // 6) masked softmax -> probs fp16
    softmax_kernel<<<dim3(SEQ, BATCH), 256>>>(Sc, mask, P);

    // 7) out = P @ Vt^T (batched, 1-product), fp32 out
    dim3 g3(HID / 128, SEQ / 128, BATCH);
    gemm_split_kernel<0, 1, false><<<g3, gblk, SMEM_P1>>>(
        P, nullptr, Vt, nullptr, nullptr, 1.0f, out, nullptr, nullptr,
        SEQ, HID, (long)SEQ * SEQ, (long)SEQ * HID, (long)SEQ * HID);
}

// round 5
// speedup vs baseline: 4.3957x; 1.3443x over previous
#include <cuda_runtime.h>
#include <cuda_fp16.h>
#include <math.h>
#include <stdint.h>

#define BATCH 8
#define SEQ   2048
#define HID   1024
#define BS    (BATCH*SEQ)

typedef __half fp16;

// ---------------------------------------------------------------------------
// Scratch (device globals — allocation is forbidden)
// ---------------------------------------------------------------------------
__device__ fp16 g_Xh[(size_t)BS * HID];
__device__ fp16 g_Wqt_hi[(size_t)HID * HID], g_Wqt_lo[(size_t)HID * HID];
__device__ fp16 g_Wkt_hi[(size_t)HID * HID], g_Wkt_lo[(size_t)HID * HID];
__device__ fp16 g_Wvt_hi[(size_t)HID * HID], g_Wvt_lo[(size_t)HID * HID];
__device__ fp16 g_Qh[(size_t)BS * HID];
__device__ fp16 g_Khi[(size_t)BS * HID], g_Klo[(size_t)BS * HID];
__device__ fp16 g_Vh[(size_t)BS * HID];
__device__ fp16 g_Vt[(size_t)BS * HID];
__device__ float g_S[(size_t)BATCH * SEQ * SEQ];
__device__ fp16 g_P[(size_t)BATCH * SEQ * SEQ];

// ---------------------------------------------------------------------------
// Helpers
// ---------------------------------------------------------------------------
__device__ __forceinline__ uint32_t smem_u32(const void* p) {
    uint32_t a;
    asm("{ .reg .u64 t; cvta.to.shared.u64 t, %1; cvt.u32.u64 %0, t; }" : "=r"(a) : "l"(p));
    return a;
}

__device__ __forceinline__ void cp_async16(uint32_t dst, const void* src) {
    asm volatile("cp.async.cg.shared.global [%0], [%1], 16;" :: "r"(dst), "l"(src));
}
__device__ __forceinline__ void cp_commit() {
    asm volatile("cp.async.commit_group;");
}
template<int N>
__device__ __forceinline__ void cp_wait() {
    asm volatile("cp.async.wait_group %0;" :: "n"(N));
}

__device__ __forceinline__ void ldsm4(uint32_t* r, uint32_t addr) {
    asm volatile("ldmatrix.sync.aligned.m8n8.x4.shared.b16 {%0,%1,%2,%3}, [%4];"
                 : "=r"(r[0]), "=r"(r[1]), "=r"(r[2]), "=r"(r[3]) : "r"(addr));
}

__device__ __forceinline__ void mma16816(float* d, const uint32_t* a, const uint32_t* b) {
    asm volatile(
        "mma.sync.aligned.m16n8k16.row.col.f32.f16.f16.f32 "
        "{%0,%1,%2,%3}, {%4,%5,%6,%7}, {%8,%9}, {%0,%1,%2,%3};"
        : "+f"(d[0]), "+f"(d[1]), "+f"(d[2]), "+f"(d[3])
        : "r"(a[0]), "r"(a[1]), "r"(a[2]), "r"(a[3]), "r"(b[0]), "r"(b[1]));
}

// SW128 swizzle of a byte offset within a tile of 128-byte rows
__device__ __forceinline__ uint32_t sw128(uint32_t off) {
    return off ^ ((off >> 3) & 0x70);
}

// ---------------------------------------------------------------------------
// Elementwise round: fp32 -> fp16
// ---------------------------------------------------------------------------
__global__ __launch_bounds__(256) void round_kernel(
    const float* __restrict__ x, fp16* __restrict__ h, long n)
{
    long i = ((long)blockIdx.x * 256 + threadIdx.x) * 4;
    if (i >= n) return;
    float4 v = *(const float4*)(x + i);
    *(half2*)(h + i)     = __floats2half2_rn(v.x, v.y);
    *(half2*)(h + i + 2) = __floats2half2_rn(v.z, v.w);
}

// W [K=H, N=H] fp32 -> Wt [N, K] (hi, lo) fp16, scaled by 32 (exact pow2).
// Scaling keeps lo-terms in fp16 normal range; epilogue multiplies by 1/32.
__global__ __launch_bounds__(256) void wtrans_kernel(
    const float* __restrict__ W, fp16* __restrict__ hi, fp16* __restrict__ lo)
{
    __shared__ float t[32][33];
    int tx = threadIdx.x, ty = threadIdx.y;
    int x0 = blockIdx.x * 32, y0 = blockIdx.y * 32;
    #pragma unroll
    for (int r = 0; r < 32; r += 8)
        t[ty + r][tx] = W[(long)(y0 + ty + r) * HID + x0 + tx];
    __syncthreads();
    #pragma unroll
    for (int r = 0; r < 32; r += 8) {
        float v = t[tx][ty + r] * 32.0f;
        long o = (long)(x0 + ty + r) * HID + y0 + tx;
        fp16 h = __float2half_rn(v);
        hi[o] = h;
        lo[o] = __float2half_rn(v - __half2float(h));
    }
}

// fp16 batched transpose: in [R, C] -> out [C, R] per batch (blockIdx.z)
__global__ __launch_bounds__(256) void btrans_kernel(
    const fp16* __restrict__ in, fp16* __restrict__ out, int R, int C)
{
    __shared__ fp16 t[32][33];
    int tx = threadIdx.x, ty = threadIdx.y;
    int x0 = blockIdx.x * 32, y0 = blockIdx.y * 32;
    in  += (long)blockIdx.z * R * C;
    out += (long)blockIdx.z * R * C;
    #pragma unroll
    for (int r = 0; r < 32; r += 8)
        t[ty + r][tx] = in[(long)(y0 + ty + r) * C + x0 + tx];
    __syncthreads();
    #pragma unroll
    for (int r = 0; r < 32; r += 8)
        out[(long)(x0 + ty + r) * R + y0 + tx] = t[tx][ty + r];
}

// ---------------------------------------------------------------------------
// HMMA fp16 GEMM (A single precision-level, B optionally hi/lo split):
//   PRODUCTS==2: C = Ah*(Bhi+Blo)^T   (2 mma products)
//   PRODUCTS==1: C = Ah*Bhi^T
// A: [M,K] K-major.  B: [N,K] K-major.  CTA tile 128x128, BK=64,
// 256 threads (8 warps, 4Mx2N, warp tile 32x64), 3-stage cp.async pipeline.
// OUTMODE: 0 = fp32, 1 = fp16 hi/lo, 2 = fp16 single.
// Epilogue: v = acc*cscale (+ bias).
// ---------------------------------------------------------------------------
#define TILE_B   16384                 // 128 rows x 128 bytes (64 fp16)
#define STAGES   3

// Load one 128x64 fp16 tile (global, row stride ldk elems) into swizzled SMEM.
__device__ __forceinline__ void load_tile_async(
    uint32_t dst, const fp16* __restrict__ src, int ldk, int tid)
{
    #pragma unroll
    for (int i = 0; i < 4; i++) {
        int s = tid + i * 256;
        int row = s >> 3, seg = s & 7;
        uint32_t off = row * 128 + seg * 16;
        cp_async16(dst + sw128(off), src + (long)row * ldk + seg * 8);
    }
}

template<int OUTMODE, int PRODUCTS, bool ADD_BIAS>
__global__ __launch_bounds__(256, 1) void gemm_split_kernel(
    const fp16* __restrict__ Ah,
    const fp16* __restrict__ Bhi, const fp16* __restrict__ Blo,
    const float* __restrict__ bias, float cscale,
    float* __restrict__ Cf, fp16* __restrict__ Chi, fp16* __restrict__ Clo,
    int K, int Ncols, long sA, long sB, long sC)
{
    constexpr int NT = (PRODUCTS == 2) ? 3 : 2;
    constexpr uint32_t STAGE_B = NT * TILE_B;
    constexpr uint32_t OFF_A   = 0;
    constexpr uint32_t OFF_BHI = 1 * TILE_B;
    constexpr uint32_t OFF_BLO = 2 * TILE_B;                 // P2 only

    extern __shared__ char smem[];
    const uint32_t tiles = (smem_u32(smem) + 1023) & ~1023u;

    const int tid = threadIdx.x;
    const int lane = tid & 31;
    const int w = tid >> 5;
    const int wm = w & 3;          // 0..3 : 32-row band
    const int wn = w >> 2;         // 0..1 : 64-col band
    const int bn = blockIdx.x, bm = blockIdx.y, bz = blockIdx.z;

    Ah  += bz * sA + (long)(bm * 128) * K;
    Bhi += bz * sB + (long)(bn * 128) * K;
    if (PRODUCTS == 2) Blo += bz * sB + (long)(bn * 128) * K;

    float acc[2][8][4];
    #pragma unroll
    for (int mt = 0; mt < 2; mt++)
        #pragma unroll
        for (int nt = 0; nt < 8; nt++)
            #pragma unroll
            for (int r = 0; r < 4; r++) acc[mt][nt][r] = 0.f;

    const int nchunks = K / 64;

    auto issue_chunk = [&](int cc) {
        const uint32_t buf = tiles + (uint32_t)(cc % STAGES) * STAGE_B;
        const long k0 = (long)cc * 64;
        load_tile_async(buf + OFF_A, Ah + k0, K, tid);
        load_tile_async(buf + OFF_BHI, Bhi + k0, K, tid);
        if (PRODUCTS == 2) load_tile_async(buf + OFF_BLO, Blo + k0, K, tid);
        cp_commit();
    };

    // prologue: stages 0,1
    issue_chunk(0);
    issue_chunk(1);

    // ldmatrix base offsets (within a tile)
    const int arow = wm * 32 + (lane & 15);            // +mt*16
    const int brow = wn * 64 + (lane & 15);            // +nt2*16
    const uint32_t kseg = (lane >> 4) * 16;            // 16B half-select

    for (int c = 0; c < nchunks; c++) {
        if (c + 2 < nchunks) { issue_chunk(c + 2); cp_wait<2>(); }
        else if (c + 1 < nchunks) { cp_wait<1>(); }
        else { cp_wait<0>(); }
        __syncthreads();

        const uint32_t buf = tiles + (uint32_t)(c % STAGES) * STAGE_B;
        const uint32_t As   = buf + OFF_A;
        const uint32_t Bs_h = buf + OFF_BHI;
        const uint32_t Bs_l = buf + OFF_BLO;

        #pragma unroll
        for (int ks = 0; ks < 4; ks++) {
            const uint32_t kb = ks * 32 + kseg;   // byte col within 128B row
            uint32_t ah[2][4];
            #pragma unroll
            for (int mt = 0; mt < 2; mt++) {
                uint32_t off = (uint32_t)(arow + mt * 16) * 128 + kb;
                ldsm4(ah[mt], As + sw128(off));
            }
            #pragma unroll
            for (int nt2 = 0; nt2 < 4; nt2++) {
                uint32_t off = (uint32_t)(brow + nt2 * 16) * 128 + kb;
                uint32_t sw = sw128(off);
                uint32_t rh[4];
                ldsm4(rh, Bs_h + sw);
                uint32_t b0h[2] = {rh[0], rh[2]}, b1h[2] = {rh[1], rh[3]};
                // interleave accumulators: reuse distance 4
                mma16816(acc[0][nt2 * 2 + 0], ah[0], b0h);
                mma16816(acc[0][nt2 * 2 + 1], ah[0], b1h);
                mma16816(acc[1][nt2 * 2 + 0], ah[1], b0h);
                mma16816(acc[1][nt2 * 2 + 1], ah[1], b1h);
                if (PRODUCTS == 2) {
                    uint32_t rl[4];
                    ldsm4(rl, Bs_l + sw);
                    uint32_t b0l[2] = {rl[0], rl[2]}, b1l[2] = {rl[1], rl[3]};
                    mma16816(acc[0][nt2 * 2 + 0], ah[0], b0l);
                    mma16816(acc[0][nt2 * 2 + 1], ah[0], b1l);
                    mma16816(acc[1][nt2 * 2 + 0], ah[1], b0l);
                    mma16816(acc[1][nt2 * 2 + 1], ah[1], b1l);
                }
            }
        }
        __syncthreads();
    }

    // ---- epilogue ----
    const int qr = lane >> 2;      // 0..7
    const int qc = lane & 3;       // 0..3
    #pragma unroll
    for (int mt = 0; mt < 2; mt++) {
        #pragma unroll
        for (int half_ = 0; half_ < 2; half_++) {   // d0,d1 vs d2,d3 (row, row+8)
            const long row = (long)(bm * 128 + wm * 32 + mt * 16 + qr + half_ * 8);
            const long cb = bz * sC + row * Ncols;
            #pragma unroll
            for (int nt = 0; nt < 8; nt++) {
                const int col = bn * 128 + wn * 64 + nt * 8 + qc * 2;
                float v0 = acc[mt][nt][half_ * 2 + 0] * cscale;
                float v1 = acc[mt][nt][half_ * 2 + 1] * cscale;
                if constexpr (ADD_BIAS) { v0 += bias[col]; v1 += bias[col + 1]; }
                if constexpr (OUTMODE == 0) {
                    *(float2*)(Cf + cb + col) = make_float2(v0, v1);
                } else if constexpr (OUTMODE == 1) {
                    fp16 h0 = __float2half_rn(v0);
                    fp16 h1 = __float2half_rn(v1);
                    fp16 l0 = __float2half_rn(v0 - __half2float(h0));
                    fp16 l1 = __float2half_rn(v1 - __half2float(h1));
                    *(half2*)(Chi + cb + col) = __halves2half2(h0, h1);
                    *(half2*)(Clo + cb + col) = __halves2half2(l0, l1);
                } else {
                    *(half2*)(Chi + cb + col) = __floats2half2_rn(v0, v1);
                }
            }
        }
    }
}

// ---------------------------------------------------------------------------
// Softmax over rows of scores [B,S,S] (already scaled by 1/32 in QK epilogue).
// Single global read (row cached in smem); emits probs as single fp16.
// ---------------------------------------------------------------------------
__global__ __launch_bounds__(256) void softmax_kernel(
    const float* __restrict__ S, const int* __restrict__ mask, fp16* __restrict__ P)
{
    const int row = blockIdx.x;
    const int b   = blockIdx.y;
    const long off = ((long)b * SEQ + row) * SEQ;
    const float* ptr = S + off;
    const int* mrow = mask + (long)b * SEQ;
    const int tid = threadIdx.x;

    __shared__ float buf[SEQ];
    __shared__ float red[256];

    float m = -INFINITY;
    #pragma unroll
    for (int k = tid * 4; k < SEQ; k += 1024) {
        float4 s = *(const float4*)(ptr + k);
        int4 mk = *(const int4*)(mrow + k);
        s.x = (mk.x == 0) ? -INFINITY : s.x;
        s.y = (mk.y == 0) ? -INFINITY : s.y;
        s.z = (mk.z == 0) ? -INFINITY : s.z;
        s.w = (mk.w == 0) ? -INFINITY : s.w;
        *(float4*)(buf + k) = s;
        m = fmaxf(m, fmaxf(fmaxf(s.x, s.y), fmaxf(s.z, s.w)));
    }
    red[tid] = m; __syncthreads();
    for (int o = 128; o > 0; o >>= 1) {
        if (tid < o) red[tid] = fmaxf(red[tid], red[tid + o]);
        __syncthreads();
    }
    m = red[0];
    __syncthreads();

    float sum = 0.f;
    #pragma unroll
    for (int k = tid * 4; k < SEQ; k += 1024) {
        float4 s = *(float4*)(buf + k);
        s.x = __expf(s.x - m); s.y = __expf(s.y - m);
        s.z = __expf(s.z - m); s.w = __expf(s.w - m);
        *(float4*)(buf + k) = s;
        sum += s.x + s.y + s.z + s.w;
    }
    red[tid] = sum; __syncthreads();
    for (int o = 128; o > 0; o >>= 1) {
        if (tid < o) red[tid] += red[tid + o];
        __syncthreads();
    }
    const float inv = 1.f / red[0];

    #pragma unroll
    for (int k = tid * 4; k < SEQ; k += 1024) {
        float4 e = *(float4*)(buf + k);
        *(half2*)(P + off + k)     = __floats2half2_rn(e.x * inv, e.y * inv);
        *(half2*)(P + off + k + 2) = __floats2half2_rn(e.z * inv, e.w * inv);
    }
}

// ---------------------------------------------------------------------------
extern "C" void kernel_launch(void* const* d_in, const int* in_sizes, int n_in,
                              void* d_out, int out_size)
{
    const float* inp  = (const float*)d_in[0];
    const int*   mask = (const int*)  d_in[1];
    const float* Wq   = (const float*)d_in[2];
    const float* bq   = (const float*)d_in[3];
    const float* Wk   = (const float*)d_in[4];
    const float* bk   = (const float*)d_in[5];
    const float* Wv   = (const float*)d_in[6];
    const float* bv   = (const float*)d_in[7];
    float* out = (float*)d_out;

    fp16 *Xh, *Wqth, *Wqtl, *Wkth, *Wktl, *Wvth, *Wvtl;
    fp16 *Qh, *Khi, *Klo, *Vh, *Vt, *P;
    float *Sc;
    cudaGetSymbolAddress((void**)&Xh, g_Xh);
    cudaGetSymbolAddress((void**)&Wqth, g_Wqt_hi); cudaGetSymbolAddress((void**)&Wqtl, g_Wqt_lo);
    cudaGetSymbolAddress((void**)&Wkth, g_Wkt_hi); cudaGetSymbolAddress((void**)&Wktl, g_Wkt_lo);
    cudaGetSymbolAddress((void**)&Wvth, g_Wvt_hi); cudaGetSymbolAddress((void**)&Wvtl, g_Wvt_lo);
    cudaGetSymbolAddress((void**)&Qh, g_Qh);
    cudaGetSymbolAddress((void**)&Khi, g_Khi);   cudaGetSymbolAddress((void**)&Klo, g_Klo);
    cudaGetSymbolAddress((void**)&Vh, g_Vh);     cudaGetSymbolAddress((void**)&Vt, g_Vt);
    cudaGetSymbolAddress((void**)&P, g_P);
    cudaGetSymbolAddress((void**)&Sc, g_S);

    const int SMEM_P2 = STAGES * 3 * TILE_B + 1024;   // 148480
    const int SMEM_P1 = STAGES * 2 * TILE_B + 1024;   // 99328
    cudaFuncSetAttribute(gemm_split_kernel<1, 2, true>,
                         cudaFuncAttributeMaxDynamicSharedMemorySize, SMEM_P2);
    cudaFuncSetAttribute(gemm_split_kernel<2, 2, true>,
                         cudaFuncAttributeMaxDynamicSharedMemorySize, SMEM_P2);
    cudaFuncSetAttribute(gemm_split_kernel<0, 2, false>,
                         cudaFuncAttributeMaxDynamicSharedMemorySize, SMEM_P2);
    cudaFuncSetAttribute(gemm_split_kernel<0, 1, false>,
                         cudaFuncAttributeMaxDynamicSharedMemorySize, SMEM_P1);

    const float inv32 = 1.0f / 32.0f;

    // 1) round input to fp16
    const long nX = (long)BS * HID;
    round_kernel<<<(unsigned)(nX / 1024), 256>>>(inp, Xh, nX);

    // 2) transpose+split weights (x32):  Wt[n][k] = 32*W[k][n]
    dim3 wgrid(HID / 32, HID / 32), wblk(32, 8);
    wtrans_kernel<<<wgrid, wblk>>>(Wq, Wqth, Wqtl);
    wtrans_kernel<<<wgrid, wblk>>>(Wk, Wkth, Wktl);
    wtrans_kernel<<<wgrid, wblk>>>(Wv, Wvth, Wvtl);

    // 3) QKV projections (2-product): acc*(1/32) + bias.
    //    Q -> single fp16; K -> hi/lo; V -> single fp16
    dim3 gblk(256);
    dim3 g1(HID / 128, BS / 128, 1);
    gemm_split_kernel<2, 2, true><<<g1, gblk, SMEM_P2>>>(
        Xh, Wqth, Wqtl, bq, inv32, nullptr, Qh, nullptr, HID, HID, 0, 0, 0);
    gemm_split_kernel<1, 2, true><<<g1, gblk, SMEM_P2>>>(
        Xh, Wkth, Wktl, bk, inv32, nullptr, Khi, Klo, HID, HID, 0, 0, 0);
    gemm_split_kernel<2, 2, true><<<g1, gblk, SMEM_P2>>>(
        Xh, Wvth, Wvtl, bv, inv32, nullptr, Vh, nullptr, HID, HID, 0, 0, 0);

    // 4) transpose V per batch: [S,H] -> [H,S]
    dim3 tgrid(HID / 32, SEQ / 32, BATCH), tblk(32, 8);
    btrans_kernel<<<tgrid, tblk>>>(Vh, Vt, SEQ, HID);

    // 5) scores = (Q @ K^T)/32 (batched, 2-product), fp32 out
    dim3 g2(SEQ / 128, SEQ / 128, BATCH);
    gemm_split_kernel<0, 2, false><<<g2, gblk, SMEM_P2>>>(
        Qh, Khi, Klo, nullptr, inv32, Sc, nullptr, nullptr,
        HID, SEQ, (long)SEQ * HID, (long)SEQ * HID, (long)SEQ * SEQ);

    // 6) masked softmax -> probs fp16
    softmax_kernel<<<dim3(SEQ, BATCH), 256>>>(Sc, mask, P);

    // 7) out = P @ Vt^T (batched, 1-product), fp32 out
    dim3 g3(HID / 128, SEQ / 128, BATCH);
    gemm_split_kernel<0, 1, false><<<g3, gblk, SMEM_P1>>>(
        P, Vt, nullptr, nullptr, 1.0f, out, nullptr, nullptr,
        SEQ, HID, (long)SEQ * SEQ, (long)SEQ * HID, (long)SEQ * HID);
}